// round 6
// baseline (speedup 1.0000x reference)
#include <cuda_runtime.h>
#include <math.h>
#include <stdint.h>

#define B_   2
#define S_   2048
#define H_   4096
#define NH   32
#define NKV  8
#define HD   128

// Scratch (static __device__ arrays: allocation-free per harness rules)
__device__ float g_q[(size_t)B_ * S_ * NH * HD];    // 67 MB
__device__ float g_k[(size_t)B_ * S_ * NKV * HD];   // 16.8 MB
__device__ float g_v[(size_t)B_ * S_ * NKV * HD];   // 16.8 MB
__device__ float g_attn[(size_t)B_ * S_ * NH * HD]; // 67 MB

__device__ __forceinline__ unsigned f2tf32(float x) {
    unsigned r;
    asm("cvt.rna.tf32.f32 %0, %1;" : "=r"(r) : "f"(x));
    return r;
}
__device__ __forceinline__ float f2tf32f(float x) {
    return __uint_as_float(f2tf32(x));
}

__device__ __forceinline__ void mma_tf32_16x8x8(
    float d[4], const unsigned a[4], const unsigned b[2])
{
    asm volatile(
        "mma.sync.aligned.m16n8k8.row.col.f32.tf32.tf32.f32 "
        "{%0,%1,%2,%3}, {%4,%5,%6,%7}, {%8,%9}, {%0,%1,%2,%3};"
        : "+f"(d[0]), "+f"(d[1]), "+f"(d[2]), "+f"(d[3])
        : "r"(a[0]), "r"(a[1]), "r"(a[2]), "r"(a[3]),
          "r"(b[0]), "r"(b[1]));
}

__device__ __forceinline__ void cp_async16(uint32_t dst_smem, const void* src) {
    asm volatile("cp.async.cg.shared.global [%0], [%1], 16;"
                 :: "r"(dst_smem), "l"(src));
}
__device__ __forceinline__ void cp_async_commit() {
    asm volatile("cp.async.commit_group;");
}
__device__ __forceinline__ void cp_async_wait0() {
    asm volatile("cp.async.wait_group 0;");
}

// ---------------------------------------------------------------------------
// TF32 tensor-core GEMM:  C[M,N] = A[M,K] * B[N,K]^T  (row-major, K-contig)
// CTA 128x128, BK=16 double-buffered, 256 threads = 8 warps (2m x 4n),
// warp tile 64x32 = 4 m16-tiles x 4 n8-tiles of mma.m16n8k8.
// smem: [row][k] stride 20 words.
// ---------------------------------------------------------------------------
#define TF_STRIDE 20
__global__ __launch_bounds__(256, 2) void gemm_tf32(
    const float* __restrict__ A, const float* __restrict__ Bm,
    float* __restrict__ C, int M, int N, int K)
{
    __shared__ unsigned As[2][128][TF_STRIDE];
    __shared__ unsigned Bs[2][128][TF_STRIDE];

    const int tid  = threadIdx.x;
    const int lane = tid & 31;
    const int warp = tid >> 5;
    const int mw   = (warp >> 2) * 64;
    const int nw   = (warp & 3) * 32;
    const int grp  = lane >> 2;
    const int thr  = lane & 3;

    const int lrow = tid >> 2;
    const int lc   = (tid & 3) << 2;
    const float* Ab = A  + (size_t)blockIdx.y * 128 * K;
    const float* Bb = Bm + (size_t)blockIdx.x * 128 * K;

    float acc[4][4][4];
#pragma unroll
    for (int mt = 0; mt < 4; mt++)
#pragma unroll
        for (int nt = 0; nt < 4; nt++)
#pragma unroll
            for (int r = 0; r < 4; r++) acc[mt][nt][r] = 0.f;

#pragma unroll
    for (int i = 0; i < 2; i++) {
        const int row = lrow + i * 64;
        float4 av = *(const float4*)(Ab + (size_t)row * K + lc);
        float4 bv = *(const float4*)(Bb + (size_t)row * K + lc);
        As[0][row][lc + 0] = f2tf32(av.x); As[0][row][lc + 1] = f2tf32(av.y);
        As[0][row][lc + 2] = f2tf32(av.z); As[0][row][lc + 3] = f2tf32(av.w);
        Bs[0][row][lc + 0] = f2tf32(bv.x); Bs[0][row][lc + 1] = f2tf32(bv.y);
        Bs[0][row][lc + 2] = f2tf32(bv.z); Bs[0][row][lc + 3] = f2tf32(bv.w);
    }
    __syncthreads();

    int buf = 0;
    for (int k0 = 0; k0 < K; k0 += 16) {
        float4 pa[2], pb[2];
        const bool has_next = (k0 + 16 < K);
        if (has_next) {
#pragma unroll
            for (int i = 0; i < 2; i++) {
                const int row = lrow + i * 64;
                pa[i] = *(const float4*)(Ab + (size_t)row * K + k0 + 16 + lc);
                pb[i] = *(const float4*)(Bb + (size_t)row * K + k0 + 16 + lc);
            }
        }

#pragma unroll
        for (int ks = 0; ks < 16; ks += 8) {
            unsigned af[4][4], bf[4][2];
#pragma unroll
            for (int mt = 0; mt < 4; mt++) {
                const int r = mw + mt * 16 + grp;
                af[mt][0] = As[buf][r][ks + thr];
                af[mt][1] = As[buf][r + 8][ks + thr];
                af[mt][2] = As[buf][r][ks + thr + 4];
                af[mt][3] = As[buf][r + 8][ks + thr + 4];
            }
#pragma unroll
            for (int nt = 0; nt < 4; nt++) {
                const int r = nw + nt * 8 + grp;
                bf[nt][0] = Bs[buf][r][ks + thr];
                bf[nt][1] = Bs[buf][r][ks + thr + 4];
            }
#pragma unroll
            for (int mt = 0; mt < 4; mt++)
#pragma unroll
                for (int nt = 0; nt < 4; nt++)
                    mma_tf32_16x8x8(acc[mt][nt], af[mt], bf[nt]);
        }

        if (has_next) {
            const int nb = buf ^ 1;
#pragma unroll
            for (int i = 0; i < 2; i++) {
                const int row = lrow + i * 64;
                As[nb][row][lc + 0] = f2tf32(pa[i].x);
                As[nb][row][lc + 1] = f2tf32(pa[i].y);
                As[nb][row][lc + 2] = f2tf32(pa[i].z);
                As[nb][row][lc + 3] = f2tf32(pa[i].w);
                Bs[nb][row][lc + 0] = f2tf32(pb[i].x);
                Bs[nb][row][lc + 1] = f2tf32(pb[i].y);
                Bs[nb][row][lc + 2] = f2tf32(pb[i].z);
                Bs[nb][row][lc + 3] = f2tf32(pb[i].w);
            }
        }
        __syncthreads();
        buf ^= 1;
    }

#pragma unroll
    for (int mt = 0; mt < 4; mt++) {
        const int r0 = blockIdx.y * 128 + mw + mt * 16 + grp;
#pragma unroll
        for (int nt = 0; nt < 4; nt++) {
            const int c = blockIdx.x * 128 + nw + nt * 8 + thr * 2;
            *(float2*)(C + (size_t)r0 * N + c) =
                make_float2(acc[mt][nt][0], acc[mt][nt][1]);
            *(float2*)(C + (size_t)(r0 + 8) * N + c) =
                make_float2(acc[mt][nt][2], acc[mt][nt][3]);
        }
    }
}

// ---------------------------------------------------------------------------
// RoPE applied in-place to q (32 heads) and k (8 heads).
// ---------------------------------------------------------------------------
__global__ void rope_kernel(float* __restrict__ q, float* __restrict__ k,
                            const int* __restrict__ pos)
{
    size_t idx = (size_t)blockIdx.x * blockDim.x + threadIdx.x;
    const size_t total = (size_t)B_ * S_ * (NH + NKV) * 64;
    if (idx >= total) return;

    const int    i    = (int)(idx & 63);
    size_t       t    = idx >> 6;
    const int    head = (int)(t % (NH + NKV));
    const size_t bs   = t / (NH + NKV);

    const float p   = (float)pos[bs];
    const float inv = expf((float)i * (-2.0f / 128.0f) * 9.2103403719761836f);
    const float ang = p * inv;
    const float c = cosf(ang), s = sinf(ang);

    float* base = (head < NH)
        ? (q + bs * (size_t)(NH * HD) + (size_t)head * HD)
        : (k + bs * (size_t)(NKV * HD) + (size_t)(head - NH) * HD);

    const float x1 = base[i];
    const float x2 = base[i + 64];
    base[i]      = x1 * c - x2 * s;
    base[i + 64] = x2 * c + x1 * s;
}

// ---------------------------------------------------------------------------
// Flash attention (tf32 MMA for QK^T and P*V; fp32 softmax), causal, GQA 4:1.
// grid = (S/64, B*NH). 256 threads = 8 warps; warp w: m-tile (w>>1)*16.
//  QK: n-quarter (w&1)*32 (4 n8-tiles);  PV: n-half (w&1)*64 (8 n8-tiles).
// Softmax: row r owned by 4 CONSECUTIVE threads (tid=4r+g) -> same warp.
// Row state (m, l) lives in registers replicated across the 4 owners;
// reductions via 2x shfl.xor. Only row_sc/row_l touch smem (for the
// differently-mapped PV/epilogue phases). 3 barriers/tile (was 5).
// K/V double-buffered: V via cp.async, K via register staging.
// ---------------------------------------------------------------------------
#define QK_STRIDE 68
#define V_STRIDE  132
#define ATTN_SMEM_FLOATS (128*QK_STRIDE + 2*128*QK_STRIDE + 2*64*V_STRIDE + 64*QK_STRIDE + 64 + 64)
#define ATTN_SMEM_BYTES  (ATTN_SMEM_FLOATS * 4)

__global__ __launch_bounds__(256) void attn_kernel(
    const float* __restrict__ Q, const float* __restrict__ K,
    const float* __restrict__ V, float* __restrict__ O)
{
    extern __shared__ float sm[];
    float* Qt     = sm;                          // [128][68] tf32 bits
    float* Kt0    = Qt  + 128 * QK_STRIDE;       // [2][128][68] tf32 bits
    float* Vs0    = Kt0 + 2 * 128 * QK_STRIDE;   // [2][64][132] fp32
    float* Ss     = Vs0 + 2 * 64 * V_STRIDE;     // [64][68] fp32 scores/probs
    float* row_sc = Ss + 64 * QK_STRIDE;         // [64] per-tile rescale
    float* row_l  = row_sc + 64;                 // [64] running denom

    const int tid  = threadIdx.x;
    const int lane = tid & 31;
    const int warp = tid >> 5;
    const int grp  = lane >> 2;
    const int thr  = lane & 3;
    const int m0   = (warp >> 1) * 16;   // warp's 16 rows
    const int nqk  = (warp & 1) * 32;    // QK col quarter
    const int npv  = (warp & 1) * 64;    // PV col half

    const int qt  = blockIdx.x;
    const int bh  = blockIdx.y;
    const int b   = bh / NH;
    const int h   = bh % NH;
    const int hk  = h / (NH / NKV);
    const float scale = 0.08838834764831845f; // 1/sqrt(128)

    // Per-thread staging coords (8 chunks of the 64x128 tile)
    const int r_ld  = tid >> 5;         // base row 0..7 (+8*it)
    const int d4_ld = (tid & 31) << 2;  // col 0..124

    // Load Q tile transposed (pre-converted to tf32 bits)
    for (int s0 = tid; s0 < 64 * 32; s0 += 256) {
        const int r  = s0 >> 5;
        const int d4 = (s0 & 31) << 2;
        const float4 v4 = *(const float4*)(Q +
            (size_t)(b * S_ + qt * 64 + r) * (NH * HD) + h * HD + d4);
        Qt[(d4 + 0) * QK_STRIDE + r] = f2tf32f(v4.x);
        Qt[(d4 + 1) * QK_STRIDE + r] = f2tf32f(v4.y);
        Qt[(d4 + 2) * QK_STRIDE + r] = f2tf32f(v4.z);
        Qt[(d4 + 3) * QK_STRIDE + r] = f2tf32f(v4.w);
    }
    // Prologue: K/V tile 0 into buffer 0
#pragma unroll
    for (int it = 0; it < 8; it++) {
        const int r = r_ld + it * 8;
        const size_t grow =
            (size_t)(b * S_ + r) * (NKV * HD) + hk * HD + d4_ld;
        const float4 kv4 = *(const float4*)(K + grow);
        Kt0[(d4_ld + 0) * QK_STRIDE + r] = f2tf32f(kv4.x);
        Kt0[(d4_ld + 1) * QK_STRIDE + r] = f2tf32f(kv4.y);
        Kt0[(d4_ld + 2) * QK_STRIDE + r] = f2tf32f(kv4.z);
        Kt0[(d4_ld + 3) * QK_STRIDE + r] = f2tf32f(kv4.w);
        *(float4*)&Vs0[r * V_STRIDE + d4_ld] = *(const float4*)(V + grow);
    }
    __syncthreads();

    float acc[8][4];   // PV accumulators, fragment layout, 8 n-tiles
#pragma unroll
    for (int nt = 0; nt < 8; nt++)
#pragma unroll
        for (int r = 0; r < 4; r++) acc[nt][r] = 0.f;

    const int r_o = tid >> 2;  // softmax owned row (4 consecutive tids/row)
    const int g   = tid & 3;   // softmax column phase (16 cols each)
    float m_run = -1e30f;      // running row max   (replicated x4 per row)
    float l_run = 0.f;         // running row denom (replicated x4 per row)

    int buf = 0;
    for (int kt = 0; kt <= qt; kt++) {
        const float* Kt = Kt0 + buf * 128 * QK_STRIDE;
        const float* Vs = Vs0 + buf * 64 * V_STRIDE;
        float* Ktn = Kt0 + (buf ^ 1) * 128 * QK_STRIDE;
        float* Vsn = Vs0 + (buf ^ 1) * 64 * V_STRIDE;

        // Issue next-tile prefetch: K -> regs, V -> cp.async into idle buffer
        const bool hn = (kt < qt);
        float4 kreg[8];
        if (hn) {
#pragma unroll
            for (int it = 0; it < 8; it++) {
                const int r = r_ld + it * 8;
                const size_t grow =
                    (size_t)(b * S_ + (kt + 1) * 64 + r) * (NKV * HD) + hk * HD + d4_ld;
                kreg[it] = *(const float4*)(K + grow);
                cp_async16((uint32_t)__cvta_generic_to_shared(&Vsn[r * V_STRIDE + d4_ld]),
                           V + grow);
            }
            cp_async_commit();
        }

        // ---- S = Q K^T via tf32 MMA (warp: m16 x n32, K=128) ----
        float sacc[4][4];
#pragma unroll
        for (int nt = 0; nt < 4; nt++)
#pragma unroll
            for (int r = 0; r < 4; r++) sacc[nt][r] = 0.f;

#pragma unroll
        for (int k0 = 0; k0 < 128; k0 += 8) {
            unsigned af[4];
            af[0] = __float_as_uint(Qt[(k0 + thr)     * QK_STRIDE + m0 + grp]);
            af[1] = __float_as_uint(Qt[(k0 + thr)     * QK_STRIDE + m0 + grp + 8]);
            af[2] = __float_as_uint(Qt[(k0 + thr + 4) * QK_STRIDE + m0 + grp]);
            af[3] = __float_as_uint(Qt[(k0 + thr + 4) * QK_STRIDE + m0 + grp + 8]);
#pragma unroll
            for (int nt = 0; nt < 4; nt++) {
                unsigned bf[2];
                const int n = nqk + nt * 8 + grp;
                bf[0] = __float_as_uint(Kt[(k0 + thr)     * QK_STRIDE + n]);
                bf[1] = __float_as_uint(Kt[(k0 + thr + 4) * QK_STRIDE + n]);
                mma_tf32_16x8x8(sacc[nt], af, bf);
            }
        }

        // Scale + causal mask + store scores (fragment layout -> Ss)
        const bool diag = (kt == qt);
        const int rr0 = m0 + grp, rr1 = m0 + grp + 8;
#pragma unroll
        for (int nt = 0; nt < 4; nt++) {
            const int cc = nqk + nt * 8 + thr * 2;
            float s00 = sacc[nt][0] * scale, s01 = sacc[nt][1] * scale;
            float s10 = sacc[nt][2] * scale, s11 = sacc[nt][3] * scale;
            if (diag) {
                if (cc     > rr0) s00 = -1e30f;
                if (cc + 1 > rr0) s01 = -1e30f;
                if (cc     > rr1) s10 = -1e30f;
                if (cc + 1 > rr1) s11 = -1e30f;
            }
            *(float2*)&Ss[rr0 * QK_STRIDE + cc] = make_float2(s00, s01);
            *(float2*)&Ss[rr1 * QK_STRIDE + cc] = make_float2(s10, s11);
        }
        __syncthreads();

        // ---- Online softmax: fully warp-local (4 owner threads per row) ----
        {
            float pm = -1e30f;
#pragma unroll
            for (int c4 = 0; c4 < 4; c4++) {
                const float4 v4 = *(const float4*)&Ss[r_o * QK_STRIDE + g * 16 + c4 * 4];
                pm = fmaxf(pm, fmaxf(fmaxf(v4.x, v4.y), fmaxf(v4.z, v4.w)));
            }
            pm = fmaxf(pm, __shfl_xor_sync(0xFFFFFFFFu, pm, 1));
            pm = fmaxf(pm, __shfl_xor_sync(0xFFFFFFFFu, pm, 2));

            const float m_new = fmaxf(m_run, pm);
            const float sc    = __expf(m_run - m_new);
            m_run = m_new;

            float psum = 0.f;
#pragma unroll
            for (int c4 = 0; c4 < 4; c4++) {
                float* p4 = &Ss[r_o * QK_STRIDE + g * 16 + c4 * 4];
                float4 v4 = *(float4*)p4;
                v4.x = __expf(v4.x - m_new); v4.y = __expf(v4.y - m_new);
                v4.z = __expf(v4.z - m_new); v4.w = __expf(v4.w - m_new);
                *(float4*)p4 = v4;
                psum += v4.x + v4.y + v4.z + v4.w;
            }
            psum += __shfl_xor_sync(0xFFFFFFFFu, psum, 1);
            psum += __shfl_xor_sync(0xFFFFFFFFu, psum, 2);
            l_run = l_run * sc + psum;

            if (g == 0) { row_sc[r_o] = sc; row_l[r_o] = l_run; }
        }
        __syncthreads();

        // ---- Rescale accumulators, then O += P * V via tf32 MMA ----
        {
            const float scl0 = row_sc[rr0];
            const float scl1 = row_sc[rr1];
#pragma unroll
            for (int nt = 0; nt < 8; nt++) {
                acc[nt][0] *= scl0; acc[nt][1] *= scl0;
                acc[nt][2] *= scl1; acc[nt][3] *= scl1;
            }
        }

#pragma unroll
        for (int k0 = 0; k0 < 64; k0 += 8) {
            unsigned af[4];
            af[0] = f2tf32(Ss[rr0 * QK_STRIDE + k0 + thr]);
            af[1] = f2tf32(Ss[rr1 * QK_STRIDE + k0 + thr]);
            af[2] = f2tf32(Ss[rr0 * QK_STRIDE + k0 + thr + 4]);
            af[3] = f2tf32(Ss[rr1 * QK_STRIDE + k0 + thr + 4]);
#pragma unroll
            for (int nt = 0; nt < 8; nt++) {
                unsigned bf[2];
                const int n = npv + nt * 8 + grp;
                bf[0] = f2tf32(Vs[(k0 + thr)     * V_STRIDE + n]);
                bf[1] = f2tf32(Vs[(k0 + thr + 4) * V_STRIDE + n]);
                mma_tf32_16x8x8(acc[nt], af, bf);
            }
        }

        // Drain prefetch: scatter K regs (as tf32) into idle transposed buffer
        if (hn) {
#pragma unroll
            for (int it = 0; it < 8; it++) {
                const int r = r_ld + it * 8;
                Ktn[(d4_ld + 0) * QK_STRIDE + r] = f2tf32f(kreg[it].x);
                Ktn[(d4_ld + 1) * QK_STRIDE + r] = f2tf32f(kreg[it].y);
                Ktn[(d4_ld + 2) * QK_STRIDE + r] = f2tf32f(kreg[it].z);
                Ktn[(d4_ld + 3) * QK_STRIDE + r] = f2tf32f(kreg[it].w);
            }
            cp_async_wait0();
        }
        __syncthreads();
        buf ^= 1;
    }

    // Epilogue: normalize and write O (fragment layout)
    {
        const int rr0 = m0 + grp, rr1 = m0 + grp + 8;
        const float inv0 = 1.0f / row_l[rr0];
        const float inv1 = 1.0f / row_l[rr1];
        const size_t orow0 = (size_t)(b * S_ + qt * 64 + rr0) * (NH * HD) + h * HD;
        const size_t orow1 = (size_t)(b * S_ + qt * 64 + rr1) * (NH * HD) + h * HD;
#pragma unroll
        for (int nt = 0; nt < 8; nt++) {
            const int cc = npv + nt * 8 + thr * 2;
            *(float2*)(O + orow0 + cc) =
                make_float2(acc[nt][0] * inv0, acc[nt][1] * inv0);
            *(float2*)(O + orow1 + cc) =
                make_float2(acc[nt][2] * inv1, acc[nt][3] * inv1);
        }
    }
}

// ---------------------------------------------------------------------------
extern "C" void kernel_launch(void* const* d_in, const int* in_sizes, int n_in,
                              void* d_out, int out_size)
{
    const float* hs  = (const float*)d_in[0];
    const int*   pos = (const int*)  d_in[1];
    const float* Wq  = (const float*)d_in[2];
    const float* Wk  = (const float*)d_in[3];
    const float* Wv  = (const float*)d_in[4];
    const float* Wo  = (const float*)d_in[5];
    float* out = (float*)d_out;

    float *q, *k, *v, *attn;
    cudaGetSymbolAddress((void**)&q,    g_q);
    cudaGetSymbolAddress((void**)&k,    g_k);
    cudaGetSymbolAddress((void**)&v,    g_v);
    cudaGetSymbolAddress((void**)&attn, g_attn);

    const int M = B_ * S_;  // 4096

    // Projections: X @ W^T  (tf32 tensor cores)
    gemm_tf32<<<dim3(H_ / 128, M / 128), 256>>>(hs, Wq, q, M, H_, H_);
    gemm_tf32<<<dim3((NKV * HD) / 128, M / 128), 256>>>(hs, Wk, k, M, NKV * HD, H_);
    gemm_tf32<<<dim3((NKV * HD) / 128, M / 128), 256>>>(hs, Wv, v, M, NKV * HD, H_);

    // RoPE on q and k
    const size_t nrope = (size_t)B_ * S_ * (NH + NKV) * 64;
    rope_kernel<<<(unsigned)((nrope + 255) / 256), 256>>>(q, k, pos);

    // Flash attention (tf32 MMA, double-buffered K/V, warp-local softmax)
    cudaFuncSetAttribute(attn_kernel,
                         cudaFuncAttributeMaxDynamicSharedMemorySize,
                         ATTN_SMEM_BYTES);
    attn_kernel<<<dim3(S_ / 64, B_ * NH), 256, ATTN_SMEM_BYTES>>>(q, k, v, attn);

    // Output projection (tf32)
    gemm_tf32<<<dim3(H_ / 128, M / 128), 256>>>(attn, Wo, out, M, H_, H_);
}